// round 5
// baseline (speedup 1.0000x reference)
#include <cuda_runtime.h>
#include <cuda_bf16.h>
#include <math.h>

// ---------------------------------------------------------------------------
// AutoEncoder3D + symmetric Chamfer loss, fully fused on-device.
// B=2, D_IN=1024, SPACE=3, BOTT=64, G=64, N=G*1024=65536 per batch.
// Inputs (metadata order): x, grid, We1,be1, We2,be2, We3,be3,
//                          Wd1,bd1, Wd2,bd2, Wd3,bd3.  Output: scalar loss.
// ---------------------------------------------------------------------------

#define NEG_INF (__int_as_float(0xff800000))

// ---------------- scratch (static __device__, no allocations) ---------------
__device__ float    g_h1part[8][2][512];     // e1 K-split partials
__device__ float    g_z[2][64];              // latent
__device__ float    g_d2arr[128 * 512];      // decoder layer-2 activations [row][512]
__device__ float    g_Y[2 * 65536 * 3];      // generated points, flat [r*3072 + col]
__device__ unsigned g_umax[2048];            // ordered-uint max_u per (b,m)
__device__ float    g_partN[512];            // per-block sum of max_u over n

// ordered-uint encoding for float atomicMax (monotone for all finite floats)
__device__ __forceinline__ unsigned enc_f(float f) {
    unsigned u = __float_as_uint(f);
    return (u & 0x80000000u) ? ~u : (u | 0x80000000u);
}
__device__ __forceinline__ float dec_f(unsigned u) {
    unsigned v = (u & 0x80000000u) ? (u & 0x7FFFFFFFu) : ~u;
    return __uint_as_float(v);
}

// ---------------- encoder layer 1: [B,3072] x [3072,512], K-split x8 --------
__global__ void k_e1(const float* __restrict__ x, const float* __restrict__ We1) {
    __shared__ float xs[384];
    const int tid = threadIdx.x;                 // 512
    const int b = blockIdx.x >> 3, kc = blockIdx.x & 7;

    if (blockIdx.x == 0) {                       // re-init umax each replay
        for (int i = tid; i < 2048; i += 512) g_umax[i] = 0u;
    }
    if (tid < 384) xs[tid] = x[b * 3072 + kc * 384 + tid];
    __syncthreads();

    const float* W = We1 + (size_t)(kc * 384) * 512 + tid;
    float a0 = 0.f, a1 = 0.f, a2 = 0.f, a3 = 0.f;
#pragma unroll 4
    for (int i = 0; i < 384; i += 4) {
        a0 = fmaf(xs[i + 0], W[(size_t)(i + 0) * 512], a0);
        a1 = fmaf(xs[i + 1], W[(size_t)(i + 1) * 512], a1);
        a2 = fmaf(xs[i + 2], W[(size_t)(i + 2) * 512], a2);
        a3 = fmaf(xs[i + 3], W[(size_t)(i + 3) * 512], a3);
    }
    g_h1part[kc][b][tid] = (a0 + a1) + (a2 + a3);
}

// ---------------- encoder layers 2+3 ----------------------------------------
__global__ void k_e23(const float* __restrict__ be1,
                      const float* __restrict__ We2, const float* __restrict__ be2,
                      const float* __restrict__ We3, const float* __restrict__ be3) {
    __shared__ float h1s[512];
    __shared__ float h2s[128];
    const int b = blockIdx.x, tid = threadIdx.x;     // 128 threads

    for (int i = tid; i < 512; i += 128) {
        float a = be1[i];
#pragma unroll
        for (int p = 0; p < 8; p++) a += g_h1part[p][b][i];
        h1s[i] = fmaxf(a, 0.f);
    }
    __syncthreads();

    {
        float c0 = 0.f, c1 = 0.f, c2 = 0.f, c3 = 0.f;
#pragma unroll 4
        for (int i = 0; i < 512; i += 4) {
            c0 = fmaf(h1s[i + 0], We2[(size_t)(i + 0) * 128 + tid], c0);
            c1 = fmaf(h1s[i + 1], We2[(size_t)(i + 1) * 128 + tid], c1);
            c2 = fmaf(h1s[i + 2], We2[(size_t)(i + 2) * 128 + tid], c2);
            c3 = fmaf(h1s[i + 3], We2[(size_t)(i + 3) * 128 + tid], c3);
        }
        h2s[tid] = fmaxf(((c0 + c1) + (c2 + c3)) + be2[tid], 0.f);
    }
    __syncthreads();

    if (tid < 64) {
        float a = be3[tid];
#pragma unroll 4
        for (int i = 0; i < 128; i++) a = fmaf(h2s[i], We3[(size_t)i * 64 + tid], a);
        g_z[b][tid] = fmaxf(a, 0.f);
    }
}

// ---------------- decoder layers 1+2: one block per (b,g) row ---------------
__global__ void k_dec12(const float* __restrict__ grid,
                        const float* __restrict__ Wd1, const float* __restrict__ bd1,
                        const float* __restrict__ Wd2, const float* __restrict__ bd2) {
    __shared__ float zi[68];
    __shared__ float d1s[128];
    const int tid = threadIdx.x;                 // 128
    const int r = blockIdx.x, b = r >> 6, g = r & 63;

    if (tid < 64)       zi[tid] = g_z[b][tid];
    else if (tid < 67)  zi[tid] = grid[g * 3 + (tid - 64)];
    __syncthreads();

    float a = bd1[tid];
#pragma unroll
    for (int i = 0; i < 67; i++) a = fmaf(zi[i], Wd1[(size_t)i * 128 + tid], a);
    d1s[tid] = fmaxf(a, 0.f);
    __syncthreads();

    float c0 = bd2[tid], c1 = bd2[tid + 128], c2 = bd2[tid + 256], c3 = bd2[tid + 384];
#pragma unroll 4
    for (int i = 0; i < 128; i++) {
        const float h = d1s[i];
        const float* W = Wd2 + (size_t)i * 512 + tid;
        c0 = fmaf(h, W[0],   c0);
        c1 = fmaf(h, W[128], c1);
        c2 = fmaf(h, W[256], c2);
        c3 = fmaf(h, W[384], c3);
    }
    float* o = g_d2arr + (size_t)r * 512 + tid;
    o[0]   = fmaxf(c0, 0.f);
    o[128] = fmaxf(c1, 0.f);
    o[256] = fmaxf(c2, 0.f);
    o[384] = fmaxf(c3, 0.f);
}

// ---------------- decoder layer 3: 128x3072x512 GEMM + tanh -----------------
// Row-blocked: every block covers all 128 rows x 32 cols so Wd3 is read once.
__global__ void k_dec3(const float* __restrict__ Wd3, const float* __restrict__ bd3) {
    __shared__ __align__(16) float As[32][132];   // [kk][row], stride 132 (16B-aligned rows)
    __shared__ float Bs[32][34];                  // [kk][col]
    const int tid = threadIdx.x;                  // 256
    const int n0 = blockIdx.x * 32;               // 96 blocks
    const int tx = tid & 15, ty = tid >> 4;       // 16x16 thread grid: 8 rows x 2 cols each

    float acc[8][2];
#pragma unroll
    for (int i = 0; i < 8; i++) { acc[i][0] = 0.f; acc[i][1] = 0.f; }

    for (int k0 = 0; k0 < 512; k0 += 32) {
        // A tile: 128x32, coalesced read, transposed store (stride-132: 4-way conflict,
        // amortized over the 32-deep FMA loop)
#pragma unroll
        for (int e = tid; e < 128 * 32; e += 256) {
            const int row = e >> 5, kk = e & 31;
            As[kk][row] = g_d2arr[(size_t)row * 512 + k0 + kk];
        }
        // B tile: 32x32 coalesced
#pragma unroll
        for (int e = tid; e < 32 * 32; e += 256) {
            const int kk = e >> 5, cc = e & 31;
            Bs[kk][cc] = Wd3[(size_t)(k0 + kk) * 3072 + n0 + cc];
        }
        __syncthreads();
#pragma unroll
        for (int kk = 0; kk < 32; kk++) {
            const float4 a0 = *(const float4*)&As[kk][ty * 8];
            const float4 a1 = *(const float4*)&As[kk][ty * 8 + 4];
            const float  b0 = Bs[kk][tx * 2];
            const float  b1 = Bs[kk][tx * 2 + 1];
            acc[0][0] = fmaf(a0.x, b0, acc[0][0]); acc[0][1] = fmaf(a0.x, b1, acc[0][1]);
            acc[1][0] = fmaf(a0.y, b0, acc[1][0]); acc[1][1] = fmaf(a0.y, b1, acc[1][1]);
            acc[2][0] = fmaf(a0.z, b0, acc[2][0]); acc[2][1] = fmaf(a0.z, b1, acc[2][1]);
            acc[3][0] = fmaf(a0.w, b0, acc[3][0]); acc[3][1] = fmaf(a0.w, b1, acc[3][1]);
            acc[4][0] = fmaf(a1.x, b0, acc[4][0]); acc[4][1] = fmaf(a1.x, b1, acc[4][1]);
            acc[5][0] = fmaf(a1.y, b0, acc[5][0]); acc[5][1] = fmaf(a1.y, b1, acc[5][1]);
            acc[6][0] = fmaf(a1.z, b0, acc[6][0]); acc[6][1] = fmaf(a1.z, b1, acc[6][1]);
            acc[7][0] = fmaf(a1.w, b0, acc[7][0]); acc[7][1] = fmaf(a1.w, b1, acc[7][1]);
        }
        __syncthreads();
    }

    const float bb0 = bd3[n0 + tx * 2], bb1 = bd3[n0 + tx * 2 + 1];
#pragma unroll
    for (int i = 0; i < 8; i++) {
        const int r = ty * 8 + i;
        float* yp = &g_Y[(size_t)r * 3072 + n0 + tx * 2];
        yp[0] = tanhf(acc[i][0] + bb0);
        yp[1] = tanhf(acc[i][1] + bb1);
    }
}

// ---------------- fused symmetric Chamfer -----------------------------------
// u = s.y - 0.5|s|^2 - 0.5|y|^2  =>  min d2 = -2 * max u, both directions.
// Block: 128 threads (4 warps). Warp w owns m in [w*256, w*256+256), 8 per lane
// (registers). Block tiles 256 n's (shared float4 {y, -0.5|y|^2}).
#define CH_NS 256
__global__ void k_chamfer(const float* __restrict__ x) {
    __shared__ float4 ys[CH_NS];
    __shared__ float  pw[CH_NS][4];
    __shared__ float  red[4];
    const int tid  = threadIdx.x;                 // 128
    const int lane = tid & 31, w = tid >> 5;
    const int bidx = blockIdx.x;                  // 512 blocks
    const int b = bidx >> 8, s = bidx & 255;
    const int n0 = s * CH_NS;

    const float* Yb = g_Y + (size_t)b * 196608;
    for (int nn = tid; nn < CH_NS; nn += 128) {
        const float yx = Yb[(size_t)(n0 + nn) * 3 + 0];
        const float yy = Yb[(size_t)(n0 + nn) * 3 + 1];
        const float yz = Yb[(size_t)(n0 + nn) * 3 + 2];
        ys[nn] = make_float4(yx, yy, yz, -0.5f * (yx * yx + yy * yy + yz * yz));
    }

    float sx[8], sy[8], sz[8], hs[8], mB[8];
    const float* xb = x + (size_t)b * 3072;
#pragma unroll
    for (int j = 0; j < 8; j++) {
        const int m = w * 256 + j * 32 + lane;
        sx[j] = xb[m * 3 + 0];
        sy[j] = xb[m * 3 + 1];
        sz[j] = xb[m * 3 + 2];
        hs[j] = -0.5f * (sx[j] * sx[j] + sy[j] * sy[j] + sz[j] * sz[j]);
        mB[j] = NEG_INF;
    }
    __syncthreads();

#pragma unroll 2
    for (int nn = 0; nn < CH_NS; nn++) {
        const float4 y = ys[nn];
        float u[8];
#pragma unroll
        for (int j = 0; j < 8; j++) {
            float t = fmaf(sx[j], y.x, hs[j]);
            t = fmaf(sy[j], y.y, t);
            t = fmaf(sz[j], y.z, t);
            u[j] = t + y.w;
            mB[j] = fmaxf(mB[j], u[j]);
        }
        float mN = fmaxf(fmaxf(fmaxf(u[0], u[1]), fmaxf(u[2], u[3])),
                         fmaxf(fmaxf(u[4], u[5]), fmaxf(u[6], u[7])));
#pragma unroll
        for (int off = 16; off; off >>= 1)
            mN = fmaxf(mN, __shfl_xor_sync(0xffffffffu, mN, off));
        if (lane == 0) pw[nn][w] = mN;
    }
    __syncthreads();

    // sum over n of (max over all m)
    float loc = 0.f;
    for (int nn = tid; nn < CH_NS; nn += 128)
        loc += fmaxf(fmaxf(pw[nn][0], pw[nn][1]), fmaxf(pw[nn][2], pw[nn][3]));
#pragma unroll
    for (int off = 16; off; off >>= 1)
        loc += __shfl_xor_sync(0xffffffffu, loc, off);
    if (lane == 0) red[w] = loc;
    __syncthreads();
    if (tid == 0) g_partN[bidx] = (red[0] + red[1]) + (red[2] + red[3]);

    // per-m running max over this block's n-slice -> global
#pragma unroll
    for (int j = 0; j < 8; j++) {
        const int m = w * 256 + j * 32 + lane;
        atomicMax(&g_umax[b * 1024 + m], enc_f(mB[j]));
    }
}

// ---------------- final reduction -------------------------------------------
__global__ void k_final(float* __restrict__ out) {
    __shared__ float red[8];
    const int tid = threadIdx.x;                 // 256
    float loc = 0.f;
    for (int i = tid; i < 2048; i += 256) loc += dec_f(g_umax[i]);
    for (int i = tid; i < 512; i += 256)  loc += g_partN[i];
#pragma unroll
    for (int off = 16; off; off >>= 1)
        loc += __shfl_xor_sync(0xffffffffu, loc, off);
    if ((tid & 31) == 0) red[tid >> 5] = loc;
    __syncthreads();
    if (tid == 0) {
        float t = 0.f;
#pragma unroll
        for (int i = 0; i < 8; i++) t += red[i];
        out[0] = -2.f * t;
    }
}

// ---------------------------------------------------------------------------
extern "C" void kernel_launch(void* const* d_in, const int* in_sizes, int n_in,
                              void* d_out, int out_size) {
    const float* x    = (const float*)d_in[0];
    const float* grid = (const float*)d_in[1];
    const float* We1  = (const float*)d_in[2];
    const float* be1  = (const float*)d_in[3];
    const float* We2  = (const float*)d_in[4];
    const float* be2  = (const float*)d_in[5];
    const float* We3  = (const float*)d_in[6];
    const float* be3  = (const float*)d_in[7];
    const float* Wd1  = (const float*)d_in[8];
    const float* bd1  = (const float*)d_in[9];
    const float* Wd2  = (const float*)d_in[10];
    const float* bd2  = (const float*)d_in[11];
    const float* Wd3  = (const float*)d_in[12];
    const float* bd3  = (const float*)d_in[13];
    float* out = (float*)d_out;

    k_e1<<<16, 512>>>(x, We1);
    k_e23<<<2, 128>>>(be1, We2, be2, We3, be3);
    k_dec12<<<128, 128>>>(grid, Wd1, bd1, Wd2, bd2);
    k_dec3<<<96, 256>>>(Wd3, bd3);
    k_chamfer<<<512, 128>>>(x);
    k_final<<<1, 256>>>(out);
}

// round 6
// speedup vs baseline: 1.2303x; 1.2303x over previous
#include <cuda_runtime.h>
#include <cuda_bf16.h>
#include <math.h>

// ---------------------------------------------------------------------------
// AutoEncoder3D + symmetric Chamfer loss, fully fused on-device.
// B=2, D_IN=1024, SPACE=3, BOTT=64, G=64, N=G*1024=65536 per batch.
// ---------------------------------------------------------------------------

#define NEG_INF (__int_as_float(0xff800000))

// ---------------- scratch (static __device__, no allocations) ---------------
__device__ float    g_h1part[8][2][512];     // e1 K-split partials
__device__ float    g_z[2][64];              // latent
__device__ float    g_d2t[512 * 128];        // decoder L2 activations, TRANSPOSED [k][row]
__device__ float    g_p3[4][128 * 3072];     // dec3 K-split partials
__device__ float    g_Y[2 * 65536 * 3];      // generated points, flat [r*3072 + col]
__device__ unsigned g_umax[2048];            // ordered-uint max_u per (b,m)
__device__ float    g_partN[512];            // per-block sum of max_u over n

// ordered-uint encoding for float atomicMax (monotone for all finite floats)
__device__ __forceinline__ unsigned enc_f(float f) {
    unsigned u = __float_as_uint(f);
    return (u & 0x80000000u) ? ~u : (u | 0x80000000u);
}
__device__ __forceinline__ float dec_f(unsigned u) {
    unsigned v = (u & 0x80000000u) ? (u & 0x7FFFFFFFu) : ~u;
    return __uint_as_float(v);
}

// ---------------- encoder layer 1: [B,3072] x [3072,512], K-split x8 --------
__global__ void k_e1(const float* __restrict__ x, const float* __restrict__ We1) {
    __shared__ float xs[384];
    const int tid = threadIdx.x;                 // 512
    const int b = blockIdx.x >> 3, kc = blockIdx.x & 7;

    if (blockIdx.x == 0) {                       // re-init umax each replay
        for (int i = tid; i < 2048; i += 512) g_umax[i] = 0u;
    }
    if (tid < 384) xs[tid] = x[b * 3072 + kc * 384 + tid];
    __syncthreads();

    const float* W = We1 + (size_t)(kc * 384) * 512 + tid;
    float a0 = 0.f, a1 = 0.f, a2 = 0.f, a3 = 0.f;
#pragma unroll 4
    for (int i = 0; i < 384; i += 4) {
        a0 = fmaf(xs[i + 0], W[(size_t)(i + 0) * 512], a0);
        a1 = fmaf(xs[i + 1], W[(size_t)(i + 1) * 512], a1);
        a2 = fmaf(xs[i + 2], W[(size_t)(i + 2) * 512], a2);
        a3 = fmaf(xs[i + 3], W[(size_t)(i + 3) * 512], a3);
    }
    g_h1part[kc][b][tid] = (a0 + a1) + (a2 + a3);
}

// ---------------- encoder layers 2+3 ----------------------------------------
__global__ void k_e23(const float* __restrict__ be1,
                      const float* __restrict__ We2, const float* __restrict__ be2,
                      const float* __restrict__ We3, const float* __restrict__ be3) {
    __shared__ float h1s[512];
    __shared__ float h2s[128];
    const int b = blockIdx.x, tid = threadIdx.x;     // 128 threads

    for (int i = tid; i < 512; i += 128) {
        float a = be1[i];
#pragma unroll
        for (int p = 0; p < 8; p++) a += g_h1part[p][b][i];
        h1s[i] = fmaxf(a, 0.f);
    }
    __syncthreads();

    {
        float c0 = 0.f, c1 = 0.f, c2 = 0.f, c3 = 0.f;
#pragma unroll 4
        for (int i = 0; i < 512; i += 4) {
            c0 = fmaf(h1s[i + 0], We2[(size_t)(i + 0) * 128 + tid], c0);
            c1 = fmaf(h1s[i + 1], We2[(size_t)(i + 1) * 128 + tid], c1);
            c2 = fmaf(h1s[i + 2], We2[(size_t)(i + 2) * 128 + tid], c2);
            c3 = fmaf(h1s[i + 3], We2[(size_t)(i + 3) * 128 + tid], c3);
        }
        h2s[tid] = fmaxf(((c0 + c1) + (c2 + c3)) + be2[tid], 0.f);
    }
    __syncthreads();

    if (tid < 64) {
        float a = be3[tid];
#pragma unroll 4
        for (int i = 0; i < 128; i++) a = fmaf(h2s[i], We3[(size_t)i * 64 + tid], a);
        g_z[b][tid] = fmaxf(a, 0.f);
    }
}

// ---------------- decoder layers 1+2: one block per (b,g) row ---------------
// Writes activations TRANSPOSED: g_d2t[k*128 + row], so dec3's A-tile fill is
// fully coalesced.
__global__ void k_dec12(const float* __restrict__ grid,
                        const float* __restrict__ Wd1, const float* __restrict__ bd1,
                        const float* __restrict__ Wd2, const float* __restrict__ bd2) {
    __shared__ float zi[68];
    __shared__ float d1s[128];
    const int tid = threadIdx.x;                 // 128
    const int r = blockIdx.x, b = r >> 6, g = r & 63;

    if (tid < 64)       zi[tid] = g_z[b][tid];
    else if (tid < 67)  zi[tid] = grid[g * 3 + (tid - 64)];
    __syncthreads();

    float a = bd1[tid];
#pragma unroll
    for (int i = 0; i < 67; i++) a = fmaf(zi[i], Wd1[(size_t)i * 128 + tid], a);
    d1s[tid] = fmaxf(a, 0.f);
    __syncthreads();

    float c0 = bd2[tid], c1 = bd2[tid + 128], c2 = bd2[tid + 256], c3 = bd2[tid + 384];
#pragma unroll 4
    for (int i = 0; i < 128; i++) {
        const float h = d1s[i];
        const float* W = Wd2 + (size_t)i * 512 + tid;
        c0 = fmaf(h, W[0],   c0);
        c1 = fmaf(h, W[128], c1);
        c2 = fmaf(h, W[256], c2);
        c3 = fmaf(h, W[384], c3);
    }
    g_d2t[(size_t)(tid)       * 128 + r] = fmaxf(c0, 0.f);
    g_d2t[(size_t)(tid + 128) * 128 + r] = fmaxf(c1, 0.f);
    g_d2t[(size_t)(tid + 256) * 128 + r] = fmaxf(c2, 0.f);
    g_d2t[(size_t)(tid + 384) * 128 + r] = fmaxf(c3, 0.f);
}

// ---------------- decoder layer 3: 128x3072x512 GEMM, 4-way K-split ---------
// Grid: 384 blocks = 96 n-tiles x 4 K-chunks. Block: 128 threads.
// Block tile: 128 rows x 32 cols x 128 k. Thread tile: 8 rows x 4 cols.
// Shared layouts are bank-conflict-free (verified: A reads hit float offsets
// {0,8,16,24} per warp -> disjoint bank quads; B reads are 128B contiguous).
__global__ void k_dec3(const float* __restrict__ Wd3) {
    __shared__ __align__(16) float As[16][132];   // float4 stride 33
    __shared__ __align__(16) float Bs[16][32];    // float4 stride 8
    const int tid = threadIdx.x;                  // 128
    const int nt = blockIdx.x % 96, kc = blockIdx.x / 96;
    const int n0 = nt * 32, kbase = kc * 128;
    const int tx = tid & 7, ty = tid >> 3;        // tx: col-group(4), ty: row-group(8)

    float acc[8][4];
#pragma unroll
    for (int i = 0; i < 8; i++)
#pragma unroll
        for (int j = 0; j < 4; j++) acc[i][j] = 0.f;

    const int kkA = tid >> 5, r4 = tid & 31;      // A fill: this thread's base
    const int kkB = tid >> 3, c4 = tid & 7;       // B fill

    for (int ks = 0; ks < 128; ks += 16) {
        // A tile: 16k x 128 rows (coalesced from transposed activations)
#pragma unroll
        for (int j = 0; j < 4; j++) {
            const int kk = kkA + j * 4;
            const float4 v = *(const float4*)&g_d2t[(size_t)(kbase + ks + kk) * 128 + r4 * 4];
            *(float4*)&As[kk][r4 * 4] = v;
        }
        // B tile: 16k x 32 cols (coalesced)
        {
            const float4 v = *(const float4*)&Wd3[(size_t)(kbase + ks + kkB) * 3072 + n0 + c4 * 4];
            *(float4*)&Bs[kkB][c4 * 4] = v;
        }
        __syncthreads();
#pragma unroll
        for (int kk = 0; kk < 16; kk++) {
            const float4 a0 = *(const float4*)&As[kk][ty * 8];
            const float4 a1 = *(const float4*)&As[kk][ty * 8 + 4];
            const float4 bv = *(const float4*)&Bs[kk][tx * 4];
            const float ar[8] = {a0.x, a0.y, a0.z, a0.w, a1.x, a1.y, a1.z, a1.w};
#pragma unroll
            for (int i = 0; i < 8; i++) {
                acc[i][0] = fmaf(ar[i], bv.x, acc[i][0]);
                acc[i][1] = fmaf(ar[i], bv.y, acc[i][1]);
                acc[i][2] = fmaf(ar[i], bv.z, acc[i][2]);
                acc[i][3] = fmaf(ar[i], bv.w, acc[i][3]);
            }
        }
        __syncthreads();
    }

    float* P = g_p3[kc];
#pragma unroll
    for (int i = 0; i < 8; i++) {
        const int row = ty * 8 + i;
        *(float4*)&P[(size_t)row * 3072 + n0 + tx * 4] =
            make_float4(acc[i][0], acc[i][1], acc[i][2], acc[i][3]);
    }
}

// ---------------- sum K-split partials + bias + tanh -> Y --------------------
__global__ void k_tanh(const float* __restrict__ bd3) {
    const int idx = blockIdx.x * 1024 + threadIdx.x * 4;   // float index, 96 blocks x 256 thr
    // process 4 float4 per thread, strided for coalescing
#pragma unroll
    for (int j = 0; j < 4; j++) {
        const int f = blockIdx.x * 4096 + j * 1024 + threadIdx.x * 4;  // flat float offset
        const int col = f % 3072;
        float4 s = *(const float4*)&g_p3[0][f];
        const float4 p1 = *(const float4*)&g_p3[1][f];
        const float4 p2 = *(const float4*)&g_p3[2][f];
        const float4 p3 = *(const float4*)&g_p3[3][f];
        const float4 bb = *(const float4*)&bd3[col];
        s.x = tanhf(((s.x + p1.x) + (p2.x + p3.x)) + bb.x);
        s.y = tanhf(((s.y + p1.y) + (p2.y + p3.y)) + bb.y);
        s.z = tanhf(((s.z + p1.z) + (p2.z + p3.z)) + bb.z);
        s.w = tanhf(((s.w + p1.w) + (p2.w + p3.w)) + bb.w);
        *(float4*)&g_Y[f] = s;
    }
    (void)idx;
}

// ---------------- fused symmetric Chamfer -----------------------------------
// u = s.y - 0.5|s|^2 - 0.5|y|^2  =>  min d2 = -2 * max u, both directions.
#define CH_NS 256
__global__ void k_chamfer(const float* __restrict__ x) {
    __shared__ float4 ys[CH_NS];
    __shared__ float  pw[CH_NS][4];
    __shared__ float  red[4];
    const int tid  = threadIdx.x;                 // 128
    const int lane = tid & 31, w = tid >> 5;
    const int bidx = blockIdx.x;                  // 512 blocks
    const int b = bidx >> 8, s = bidx & 255;
    const int n0 = s * CH_NS;

    const float* Yb = g_Y + (size_t)b * 196608;
    for (int nn = tid; nn < CH_NS; nn += 128) {
        const float yx = Yb[(size_t)(n0 + nn) * 3 + 0];
        const float yy = Yb[(size_t)(n0 + nn) * 3 + 1];
        const float yz = Yb[(size_t)(n0 + nn) * 3 + 2];
        ys[nn] = make_float4(yx, yy, yz, -0.5f * (yx * yx + yy * yy + yz * yz));
    }

    float sx[8], sy[8], sz[8], hs[8], mB[8];
    const float* xb = x + (size_t)b * 3072;
#pragma unroll
    for (int j = 0; j < 8; j++) {
        const int m = w * 256 + j * 32 + lane;
        sx[j] = xb[m * 3 + 0];
        sy[j] = xb[m * 3 + 1];
        sz[j] = xb[m * 3 + 2];
        hs[j] = -0.5f * (sx[j] * sx[j] + sy[j] * sy[j] + sz[j] * sz[j]);
        mB[j] = NEG_INF;
    }
    __syncthreads();

#pragma unroll 2
    for (int nn = 0; nn < CH_NS; nn++) {
        const float4 y = ys[nn];
        float u[8];
#pragma unroll
        for (int j = 0; j < 8; j++) {
            float t = fmaf(sx[j], y.x, hs[j]);
            t = fmaf(sy[j], y.y, t);
            t = fmaf(sz[j], y.z, t);
            u[j] = t + y.w;
            mB[j] = fmaxf(mB[j], u[j]);
        }
        float mN = fmaxf(fmaxf(fmaxf(u[0], u[1]), fmaxf(u[2], u[3])),
                         fmaxf(fmaxf(u[4], u[5]), fmaxf(u[6], u[7])));
#pragma unroll
        for (int off = 16; off; off >>= 1)
            mN = fmaxf(mN, __shfl_xor_sync(0xffffffffu, mN, off));
        if (lane == 0) pw[nn][w] = mN;
    }
    __syncthreads();

    // sum over n of (max over all m)
    float loc = 0.f;
    for (int nn = tid; nn < CH_NS; nn += 128)
        loc += fmaxf(fmaxf(pw[nn][0], pw[nn][1]), fmaxf(pw[nn][2], pw[nn][3]));
#pragma unroll
    for (int off = 16; off; off >>= 1)
        loc += __shfl_xor_sync(0xffffffffu, loc, off);
    if (lane == 0) red[w] = loc;
    __syncthreads();
    if (tid == 0) g_partN[bidx] = (red[0] + red[1]) + (red[2] + red[3]);

    // per-m running max over this block's n-slice -> global
#pragma unroll
    for (int j = 0; j < 8; j++) {
        const int m = w * 256 + j * 32 + lane;
        atomicMax(&g_umax[b * 1024 + m], enc_f(mB[j]));
    }
}

// ---------------- final reduction -------------------------------------------
__global__ void k_final(float* __restrict__ out) {
    __shared__ float red[8];
    const int tid = threadIdx.x;                 // 256
    float loc = 0.f;
    for (int i = tid; i < 2048; i += 256) loc += dec_f(g_umax[i]);
    for (int i = tid; i < 512; i += 256)  loc += g_partN[i];
#pragma unroll
    for (int off = 16; off; off >>= 1)
        loc += __shfl_xor_sync(0xffffffffu, loc, off);
    if ((tid & 31) == 0) red[tid >> 5] = loc;
    __syncthreads();
    if (tid == 0) {
        float t = 0.f;
#pragma unroll
        for (int i = 0; i < 8; i++) t += red[i];
        out[0] = -2.f * t;
    }
}

// ---------------------------------------------------------------------------
extern "C" void kernel_launch(void* const* d_in, const int* in_sizes, int n_in,
                              void* d_out, int out_size) {
    const float* x    = (const float*)d_in[0];
    const float* grid = (const float*)d_in[1];
    const float* We1  = (const float*)d_in[2];
    const float* be1  = (const float*)d_in[3];
    const float* We2  = (const float*)d_in[4];
    const float* be2  = (const float*)d_in[5];
    const float* We3  = (const float*)d_in[6];
    const float* be3  = (const float*)d_in[7];
    const float* Wd1  = (const float*)d_in[8];
    const float* bd1  = (const float*)d_in[9];
    const float* Wd2  = (const float*)d_in[10];
    const float* bd2  = (const float*)d_in[11];
    const float* Wd3  = (const float*)d_in[12];
    const float* bd3  = (const float*)d_in[13];
    float* out = (float*)d_out;

    k_e1<<<16, 512>>>(x, We1);
    k_e23<<<2, 128>>>(be1, We2, be2, We3, be3);
    k_dec12<<<128, 128>>>(grid, Wd1, bd1, Wd2, bd2);
    k_dec3<<<384, 128>>>(Wd3);
    k_tanh<<<96, 256>>>(bd3);
    k_chamfer<<<512, 128>>>(x);
    k_final<<<1, 256>>>(out);
}

// round 7
// speedup vs baseline: 1.5456x; 1.2563x over previous
#include <cuda_runtime.h>
#include <cuda_bf16.h>
#include <math.h>

// ---------------------------------------------------------------------------
// AutoEncoder3D + symmetric Chamfer loss, fully fused on-device.
// B=2, D_IN=1024, SPACE=3, BOTT=64, G=64, N=G*1024=65536 per batch.
// ---------------------------------------------------------------------------

#define NEG_INF (__int_as_float(0xff800000))

// ---------------- packed f32x2 helpers (Blackwell FFMA2 path) ----------------
typedef unsigned long long u64t;
__device__ __forceinline__ u64t pk2(float lo, float hi) {
    u64t r; asm("mov.b64 %0, {%1, %2};" : "=l"(r) : "f"(lo), "f"(hi)); return r;
}
__device__ __forceinline__ void upk2(float& lo, float& hi, u64t v) {
    asm("mov.b64 {%0, %1}, %2;" : "=f"(lo), "=f"(hi) : "l"(v));
}
__device__ __forceinline__ u64t fma2(u64t a, u64t b, u64t c) {
    u64t d; asm("fma.rn.f32x2 %0, %1, %2, %3;" : "=l"(d) : "l"(a), "l"(b), "l"(c)); return d;
}
__device__ __forceinline__ u64t add2(u64t a, u64t b) {
    u64t d; asm("add.rn.f32x2 %0, %1, %2;" : "=l"(d) : "l"(a), "l"(b)); return d;
}

// ---------------- scratch (static __device__, no allocations) ---------------
__device__ float    g_h1part[16][2][512];    // e1 K-split partials
__device__ float    g_z[2][64];              // latent
__device__ float    g_d2t[512 * 128];        // decoder L2 activations, TRANSPOSED [k][row]
__device__ float    g_p3[8][128 * 3072];     // dec3 K-split partials
__device__ unsigned g_umax[2048];            // ordered-uint max_u per (b,m)
__device__ float    g_partN[512];            // per-block sum of max_u over n

// ordered-uint encoding for float atomicMax (monotone for all finite floats)
__device__ __forceinline__ unsigned enc_f(float f) {
    unsigned u = __float_as_uint(f);
    return (u & 0x80000000u) ? ~u : (u | 0x80000000u);
}
__device__ __forceinline__ float dec_f(unsigned u) {
    unsigned v = (u & 0x80000000u) ? (u & 0x7FFFFFFFu) : ~u;
    return __uint_as_float(v);
}

// ---------------- encoder layer 1: [B,3072] x [3072,512], K-split x16 -------
__global__ void k_e1(const float* __restrict__ x, const float* __restrict__ We1) {
    __shared__ float xs[192];
    const int tid = threadIdx.x;                 // 512
    const int b = blockIdx.x >> 4, kc = blockIdx.x & 15;

    if (blockIdx.x == 0) {                       // re-init umax each replay
        for (int i = tid; i < 2048; i += 512) g_umax[i] = 0u;
    }
    if (tid < 192) xs[tid] = x[b * 3072 + kc * 192 + tid];
    __syncthreads();

    const float* W = We1 + (size_t)(kc * 192) * 512 + tid;
    float a0 = 0.f, a1 = 0.f, a2 = 0.f, a3 = 0.f;
#pragma unroll 4
    for (int i = 0; i < 192; i += 4) {
        a0 = fmaf(xs[i + 0], W[(size_t)(i + 0) * 512], a0);
        a1 = fmaf(xs[i + 1], W[(size_t)(i + 1) * 512], a1);
        a2 = fmaf(xs[i + 2], W[(size_t)(i + 2) * 512], a2);
        a3 = fmaf(xs[i + 3], W[(size_t)(i + 3) * 512], a3);
    }
    g_h1part[kc][b][tid] = (a0 + a1) + (a2 + a3);
}

// ---------------- encoder layers 2+3 ----------------------------------------
__global__ void k_e23(const float* __restrict__ be1,
                      const float* __restrict__ We2, const float* __restrict__ be2,
                      const float* __restrict__ We3, const float* __restrict__ be3) {
    __shared__ float h1s[512];
    __shared__ float h2s[128];
    const int b = blockIdx.x, tid = threadIdx.x;     // 128 threads

    for (int i = tid; i < 512; i += 128) {
        float a = be1[i];
#pragma unroll
        for (int p = 0; p < 16; p++) a += g_h1part[p][b][i];
        h1s[i] = fmaxf(a, 0.f);
    }
    __syncthreads();

    {
        float c0 = 0.f, c1 = 0.f, c2 = 0.f, c3 = 0.f;
#pragma unroll 4
        for (int i = 0; i < 512; i += 4) {
            c0 = fmaf(h1s[i + 0], We2[(size_t)(i + 0) * 128 + tid], c0);
            c1 = fmaf(h1s[i + 1], We2[(size_t)(i + 1) * 128 + tid], c1);
            c2 = fmaf(h1s[i + 2], We2[(size_t)(i + 2) * 128 + tid], c2);
            c3 = fmaf(h1s[i + 3], We2[(size_t)(i + 3) * 128 + tid], c3);
        }
        h2s[tid] = fmaxf(((c0 + c1) + (c2 + c3)) + be2[tid], 0.f);
    }
    __syncthreads();

    if (tid < 64) {
        float a = be3[tid];
#pragma unroll 4
        for (int i = 0; i < 128; i++) a = fmaf(h2s[i], We3[(size_t)i * 64 + tid], a);
        g_z[b][tid] = fmaxf(a, 0.f);
    }
}

// ---------------- decoder layers 1+2: one block per (b,g) row ---------------
// Writes activations TRANSPOSED: g_d2t[k*128 + row].
__global__ void k_dec12(const float* __restrict__ grid,
                        const float* __restrict__ Wd1, const float* __restrict__ bd1,
                        const float* __restrict__ Wd2, const float* __restrict__ bd2) {
    __shared__ float zi[68];
    __shared__ float d1s[128];
    const int tid = threadIdx.x;                 // 128
    const int r = blockIdx.x, b = r >> 6, g = r & 63;

    if (tid < 64)       zi[tid] = g_z[b][tid];
    else if (tid < 67)  zi[tid] = grid[g * 3 + (tid - 64)];
    __syncthreads();

    float a = bd1[tid];
#pragma unroll
    for (int i = 0; i < 67; i++) a = fmaf(zi[i], Wd1[(size_t)i * 128 + tid], a);
    d1s[tid] = fmaxf(a, 0.f);
    __syncthreads();

    float c0 = bd2[tid], c1 = bd2[tid + 128], c2 = bd2[tid + 256], c3 = bd2[tid + 384];
#pragma unroll 4
    for (int i = 0; i < 128; i++) {
        const float h = d1s[i];
        const float* W = Wd2 + (size_t)i * 512 + tid;
        c0 = fmaf(h, W[0],   c0);
        c1 = fmaf(h, W[128], c1);
        c2 = fmaf(h, W[256], c2);
        c3 = fmaf(h, W[384], c3);
    }
    g_d2t[(size_t)(tid)       * 128 + r] = fmaxf(c0, 0.f);
    g_d2t[(size_t)(tid + 128) * 128 + r] = fmaxf(c1, 0.f);
    g_d2t[(size_t)(tid + 256) * 128 + r] = fmaxf(c2, 0.f);
    g_d2t[(size_t)(tid + 384) * 128 + r] = fmaxf(c3, 0.f);
}

// ---------------- decoder layer 3: 128x3072x512 GEMM, 8-way K-split ---------
// Grid: 768 blocks = 96 n-tiles x 8 K-chunks of 64. Block: 128 threads.
// Thread tile: 8 rows x 4 cols, packed f32x2 accumulators (FFMA2).
__global__ void k_dec3(const float* __restrict__ Wd3) {
    __shared__ __align__(16) float As[16][132];   // float4 stride 33
    __shared__ __align__(16) float Bs[16][32];
    const int tid = threadIdx.x;                  // 128
    const int nt = blockIdx.x % 96, kc = blockIdx.x / 96;
    const int n0 = nt * 32, kbase = kc * 64;
    const int tx = tid & 7, ty = tid >> 3;        // tx: col-group(4), ty: row-group(8)

    u64t acc01[8], acc23[8];
#pragma unroll
    for (int i = 0; i < 8; i++) { acc01[i] = 0ull; acc23[i] = 0ull; }

    const int kkA = tid >> 5, r4 = tid & 31;
    const int kkB = tid >> 3, c4 = tid & 7;

    for (int ks = 0; ks < 64; ks += 16) {
#pragma unroll
        for (int j = 0; j < 4; j++) {
            const int kk = kkA + j * 4;
            const float4 v = *(const float4*)&g_d2t[(size_t)(kbase + ks + kk) * 128 + r4 * 4];
            *(float4*)&As[kk][r4 * 4] = v;
        }
        {
            const float4 v = *(const float4*)&Wd3[(size_t)(kbase + ks + kkB) * 3072 + n0 + c4 * 4];
            *(float4*)&Bs[kkB][c4 * 4] = v;
        }
        __syncthreads();
#pragma unroll
        for (int kk = 0; kk < 16; kk++) {
            const float4 a0 = *(const float4*)&As[kk][ty * 8];
            const float4 a1 = *(const float4*)&As[kk][ty * 8 + 4];
            const ulonglong2 bv = *(const ulonglong2*)&Bs[kk][tx * 4];
            const float ar[8] = {a0.x, a0.y, a0.z, a0.w, a1.x, a1.y, a1.z, a1.w};
#pragma unroll
            for (int i = 0; i < 8; i++) {
                const u64t ad = pk2(ar[i], ar[i]);
                acc01[i] = fma2(ad, bv.x, acc01[i]);
                acc23[i] = fma2(ad, bv.y, acc23[i]);
            }
        }
        __syncthreads();
    }

    float* P = g_p3[kc];
#pragma unroll
    for (int i = 0; i < 8; i++) {
        const int row = ty * 8 + i;
        float v0, v1, v2, v3;
        upk2(v0, v1, acc01[i]);
        upk2(v2, v3, acc23[i]);
        *(float4*)&P[(size_t)row * 3072 + n0 + tx * 4] = make_float4(v0, v1, v2, v3);
    }
}

// ---------------- fused partial-sum + bias + tanh + symmetric Chamfer -------
// u = s.y - 0.5|s|^2 - 0.5|y|^2  =>  min d2 = -2 * max u, both directions.
// Inner loop: packed f32x2 (2 targets per instruction).
#define CH_NS 256
__global__ void k_chamfer(const float* __restrict__ x, const float* __restrict__ bd3) {
    __shared__ __align__(16) float ys2[CH_NS][8]; // {yx,yx,yy,yy,yz,yz,yw,yw}
    __shared__ __align__(16) float ysc[CH_NS * 3];
    __shared__ float pw[CH_NS][4];
    __shared__ float red[4];
    const int tid  = threadIdx.x;                 // 128
    const int lane = tid & 31, w = tid >> 5;
    const int bidx = blockIdx.x;                  // 512 blocks
    const int b = bidx >> 8, s = bidx & 255;
    const int n0 = s * CH_NS;

    // --- phase 1: Y = tanh(sum of 8 K-split partials + bias) for 256 points -
    {
        const int gf0 = b * 196608 + n0 * 3;           // flat float base (mult of 4)
        const int col0 = (n0 & 1023) * 3;              // bias column base (mult of 4)
        if (tid < 192) {
            const int o = tid * 4;
            float4 sacc = *(const float4*)&g_p3[0][gf0 + o];
#pragma unroll
            for (int p = 1; p < 8; p++) {
                const float4 q = *(const float4*)&g_p3[p][gf0 + o];
                sacc.x += q.x; sacc.y += q.y; sacc.z += q.z; sacc.w += q.w;
            }
            const float4 bb = *(const float4*)&bd3[col0 + o];
            sacc.x = tanhf(sacc.x + bb.x);
            sacc.y = tanhf(sacc.y + bb.y);
            sacc.z = tanhf(sacc.z + bb.z);
            sacc.w = tanhf(sacc.w + bb.w);
            *(float4*)&ysc[o] = sacc;
        }
    }
    __syncthreads();
    for (int nn = tid; nn < CH_NS; nn += 128) {
        const float yx = ysc[nn * 3 + 0];
        const float yy = ysc[nn * 3 + 1];
        const float yz = ysc[nn * 3 + 2];
        const float yw = -0.5f * (yx * yx + yy * yy + yz * yz);
        *(float4*)&ys2[nn][0] = make_float4(yx, yx, yy, yy);
        *(float4*)&ys2[nn][4] = make_float4(yz, yz, yw, yw);
    }

    // --- phase 2: per-lane targets, 8 m's as 4 packed pairs ------------------
    u64t sx2[4], sy2[4], sz2[4], hs2[4];
    float mBlo[4], mBhi[4];
    const float* xb = x + (size_t)b * 3072;
#pragma unroll
    for (int g = 0; g < 4; g++) {
        const int m0 = w * 256 + (2 * g) * 32 + lane;
        const int m1 = m0 + 32;
        const float ax = xb[m0 * 3 + 0], ay = xb[m0 * 3 + 1], az = xb[m0 * 3 + 2];
        const float cx = xb[m1 * 3 + 0], cy = xb[m1 * 3 + 1], cz = xb[m1 * 3 + 2];
        sx2[g] = pk2(ax, cx);
        sy2[g] = pk2(ay, cy);
        sz2[g] = pk2(az, cz);
        hs2[g] = pk2(-0.5f * (ax * ax + ay * ay + az * az),
                     -0.5f * (cx * cx + cy * cy + cz * cz));
        mBlo[g] = NEG_INF; mBhi[g] = NEG_INF;
    }
    __syncthreads();

#pragma unroll 2
    for (int nn = 0; nn < CH_NS; nn++) {
        const ulonglong2 yA = *(const ulonglong2*)&ys2[nn][0];  // yx2, yy2
        const ulonglong2 yB = *(const ulonglong2*)&ys2[nn][4];  // yz2, yw2
        float ul[4], uh[4];
#pragma unroll
        for (int g = 0; g < 4; g++) {
            u64t t = fma2(sx2[g], yA.x, hs2[g]);
            t = fma2(sy2[g], yA.y, t);
            t = fma2(sz2[g], yB.x, t);
            t = add2(t, yB.y);
            upk2(ul[g], uh[g], t);
            mBlo[g] = fmaxf(mBlo[g], ul[g]);
            mBhi[g] = fmaxf(mBhi[g], uh[g]);
        }
        float mN = fmaxf(fmaxf(fmaxf(ul[0], uh[0]), fmaxf(ul[1], uh[1])),
                         fmaxf(fmaxf(ul[2], uh[2]), fmaxf(ul[3], uh[3])));
#pragma unroll
        for (int off = 16; off; off >>= 1)
            mN = fmaxf(mN, __shfl_xor_sync(0xffffffffu, mN, off));
        if (lane == 0) pw[nn][w] = mN;
    }
    __syncthreads();

    // sum over n of (max over all m)
    float loc = 0.f;
    for (int nn = tid; nn < CH_NS; nn += 128)
        loc += fmaxf(fmaxf(pw[nn][0], pw[nn][1]), fmaxf(pw[nn][2], pw[nn][3]));
#pragma unroll
    for (int off = 16; off; off >>= 1)
        loc += __shfl_xor_sync(0xffffffffu, loc, off);
    if (lane == 0) red[w] = loc;
    __syncthreads();
    if (tid == 0) g_partN[bidx] = (red[0] + red[1]) + (red[2] + red[3]);

    // per-m running max over this block's n-slice -> global
#pragma unroll
    for (int g = 0; g < 4; g++) {
        const int m0 = w * 256 + (2 * g) * 32 + lane;
        atomicMax(&g_umax[b * 1024 + m0],      enc_f(mBlo[g]));
        atomicMax(&g_umax[b * 1024 + m0 + 32], enc_f(mBhi[g]));
    }
}

// ---------------- final reduction -------------------------------------------
__global__ void k_final(float* __restrict__ out) {
    __shared__ float red[8];
    const int tid = threadIdx.x;                 // 256
    float loc = 0.f;
    for (int i = tid; i < 2048; i += 256) loc += dec_f(g_umax[i]);
    for (int i = tid; i < 512; i += 256)  loc += g_partN[i];
#pragma unroll
    for (int off = 16; off; off >>= 1)
        loc += __shfl_xor_sync(0xffffffffu, loc, off);
    if ((tid & 31) == 0) red[tid >> 5] = loc;
    __syncthreads();
    if (tid == 0) {
        float t = 0.f;
#pragma unroll
        for (int i = 0; i < 8; i++) t += red[i];
        out[0] = -2.f * t;
    }
}

// ---------------------------------------------------------------------------
extern "C" void kernel_launch(void* const* d_in, const int* in_sizes, int n_in,
                              void* d_out, int out_size) {
    const float* x    = (const float*)d_in[0];
    const float* grid = (const float*)d_in[1];
    const float* We1  = (const float*)d_in[2];
    const float* be1  = (const float*)d_in[3];
    const float* We2  = (const float*)d_in[4];
    const float* be2  = (const float*)d_in[5];
    const float* We3  = (const float*)d_in[6];
    const float* be3  = (const float*)d_in[7];
    const float* Wd1  = (const float*)d_in[8];
    const float* bd1  = (const float*)d_in[9];
    const float* Wd2  = (const float*)d_in[10];
    const float* bd2  = (const float*)d_in[11];
    const float* Wd3  = (const float*)d_in[12];
    const float* bd3  = (const float*)d_in[13];
    float* out = (float*)d_out;

    k_e1<<<32, 512>>>(x, We1);
    k_e23<<<2, 128>>>(be1, We2, be2, We3, be3);
    k_dec12<<<128, 128>>>(grid, Wd1, bd1, Wd2, bd2);
    k_dec3<<<768, 128>>>(Wd3);
    k_chamfer<<<512, 128>>>(x, bd3);
    k_final<<<1, 256>>>(out);
}